// round 1
// baseline (speedup 1.0000x reference)
#include <cuda_runtime.h>
#include <math.h>

#define D_MODEL 1024
#define NHEADS  16
#define DK      64
#define BATCH   2
#define SEQ     2048
#define MROWS   (BATCH*SEQ)   // 4096

// Scratch (device globals: allocation-free per harness rules)
__device__ float g_Q[MROWS * D_MODEL];
__device__ float g_K[MROWS * D_MODEL];
__device__ float g_V[MROWS * D_MODEL];
__device__ float g_O[MROWS * D_MODEL];

// ----------------------------------------------------------------------------
// SGEMM: C[M,N] = A[M,K] * B[N,K]^T   (A, B row-major; all dims multiples of 128/16)
// 128x128 block, BK=16, 256 threads, 8x8 per-thread micro-tile.
// ----------------------------------------------------------------------------
__global__ __launch_bounds__(256, 2)
void sgemm_nt(const float* __restrict__ A, const float* __restrict__ Bm,
              float* __restrict__ C, int M, int N, int K)
{
    __shared__ float As[16][128];
    __shared__ float Bs[16][128];

    const int tid = threadIdx.x;
    const int ty  = tid >> 4;        // 0..15
    const int tx  = tid & 15;        // 0..15

    const float* Ab = A  + (size_t)blockIdx.y * 128 * K;
    const float* Bb = Bm + (size_t)blockIdx.x * 128 * K;

    float acc[8][8];
#pragma unroll
    for (int i = 0; i < 8; i++)
#pragma unroll
        for (int j = 0; j < 8; j++) acc[i][j] = 0.f;

    for (int kk = 0; kk < K; kk += 16) {
        // Load A/B tiles (each thread: 2 float4 from A, 2 from B), store transposed.
#pragma unroll
        for (int l = 0; l < 2; l++) {
            int idx = tid + l * 256;      // 0..511
            int r   = idx >> 2;           // 0..127
            int c   = (idx & 3) * 4;      // 0,4,8,12
            float4 va = *(const float4*)(Ab + (size_t)r * K + kk + c);
            As[c + 0][r] = va.x; As[c + 1][r] = va.y;
            As[c + 2][r] = va.z; As[c + 3][r] = va.w;
            float4 vb = *(const float4*)(Bb + (size_t)r * K + kk + c);
            Bs[c + 0][r] = vb.x; Bs[c + 1][r] = vb.y;
            Bs[c + 2][r] = vb.z; Bs[c + 3][r] = vb.w;
        }
        __syncthreads();

#pragma unroll
        for (int k = 0; k < 16; k++) {
            float a[8], b[8];
            *(float4*)(a)     = *(const float4*)(&As[k][ty * 8]);
            *(float4*)(a + 4) = *(const float4*)(&As[k][ty * 8 + 4]);
            *(float4*)(b)     = *(const float4*)(&Bs[k][tx * 8]);
            *(float4*)(b + 4) = *(const float4*)(&Bs[k][tx * 8 + 4]);
#pragma unroll
            for (int i = 0; i < 8; i++)
#pragma unroll
                for (int j = 0; j < 8; j++)
                    acc[i][j] += a[i] * b[j];
        }
        __syncthreads();
    }

#pragma unroll
    for (int i = 0; i < 8; i++) {
        float* cp = C + (size_t)(blockIdx.y * 128 + ty * 8 + i) * N
                      + blockIdx.x * 128 + tx * 8;
        *(float4*)(cp)     = make_float4(acc[i][0], acc[i][1], acc[i][2], acc[i][3]);
        *(float4*)(cp + 4) = make_float4(acc[i][4], acc[i][5], acc[i][6], acc[i][7]);
    }
}

// ----------------------------------------------------------------------------
// Flash attention (fp32, causal). Br=Bc=64, dk=64, 256 threads, 4x4 per-thread.
// Q/K/V laid out [b, s, h*dk]; per-head row stride = D_MODEL.
// ----------------------------------------------------------------------------
#define SMLD 65   // padded row length to dodge bank conflicts

__global__ __launch_bounds__(256)
void attn_fwd(const float* __restrict__ Q, const float* __restrict__ K,
              const float* __restrict__ V, float* __restrict__ O)
{
    extern __shared__ float smem[];
    float* Qs = smem;                 // [64][65]
    float* Ks = smem + 64 * SMLD;     // [64][65]
    float* Vs = smem + 2 * 64 * SMLD; // [64][65]
    float* Ps = smem + 3 * 64 * SMLD; // [64][65]

    const int qb = blockIdx.x;        // 0..31
    const int h  = blockIdx.y;        // 0..15
    const int b  = blockIdx.z;        // 0..1
    const int tid = threadIdx.x;
    const int ty = tid >> 4;          // 0..15 (owns rows ty*4..+3)
    const int tx = tid & 15;          // 0..15 (owns cols tx*4..+3)

    const size_t base = (size_t)b * SEQ * D_MODEL + (size_t)h * DK;
    const float* Qg = Q + base + (size_t)qb * 64 * D_MODEL;
    const float scale = 0.125f;       // 1/sqrt(64)

    // Load Q tile (pre-scaled)
#pragma unroll
    for (int l = 0; l < 4; l++) {
        int idx = tid + l * 256;      // 0..1023 float4 slots
        int r = idx >> 4;
        int c = (idx & 15) * 4;
        float4 v = *(const float4*)(Qg + (size_t)r * D_MODEL + c);
        Qs[r * SMLD + c + 0] = v.x * scale;
        Qs[r * SMLD + c + 1] = v.y * scale;
        Qs[r * SMLD + c + 2] = v.z * scale;
        Qs[r * SMLD + c + 3] = v.w * scale;
    }

    float mrow[4], lrow[4], acc[4][4];
#pragma unroll
    for (int i = 0; i < 4; i++) {
        mrow[i] = -1e30f; lrow[i] = 0.f;
#pragma unroll
        for (int j = 0; j < 4; j++) acc[i][j] = 0.f;
    }
    __syncthreads();

    for (int j = 0; j <= qb; j++) {
        const float* Kg = K + base + (size_t)j * 64 * D_MODEL;
        const float* Vg = V + base + (size_t)j * 64 * D_MODEL;
#pragma unroll
        for (int l = 0; l < 4; l++) {
            int idx = tid + l * 256;
            int r = idx >> 4;
            int c = (idx & 15) * 4;
            float4 vk = *(const float4*)(Kg + (size_t)r * D_MODEL + c);
            Ks[r * SMLD + c + 0] = vk.x; Ks[r * SMLD + c + 1] = vk.y;
            Ks[r * SMLD + c + 2] = vk.z; Ks[r * SMLD + c + 3] = vk.w;
            float4 vv = *(const float4*)(Vg + (size_t)r * D_MODEL + c);
            Vs[r * SMLD + c + 0] = vv.x; Vs[r * SMLD + c + 1] = vv.y;
            Vs[r * SMLD + c + 2] = vv.z; Vs[r * SMLD + c + 3] = vv.w;
        }
        __syncthreads();

        // S = Q * K^T (4x4 micro-tile)
        float s[4][4];
#pragma unroll
        for (int i = 0; i < 4; i++)
#pragma unroll
            for (int jj = 0; jj < 4; jj++) s[i][jj] = 0.f;

#pragma unroll 8
        for (int k = 0; k < 64; k++) {
            float aq[4], bk[4];
#pragma unroll
            for (int i = 0; i < 4; i++)  aq[i]  = Qs[(ty * 4 + i) * SMLD + k];
#pragma unroll
            for (int jj = 0; jj < 4; jj++) bk[jj] = Ks[(tx * 4 + jj) * SMLD + k];
#pragma unroll
            for (int i = 0; i < 4; i++)
#pragma unroll
                for (int jj = 0; jj < 4; jj++)
                    s[i][jj] += aq[i] * bk[jj];
        }

        // Causal mask: only the diagonal block needs it
        if (j == qb) {
#pragma unroll
            for (int i = 0; i < 4; i++)
#pragma unroll
                for (int jj = 0; jj < 4; jj++)
                    if (tx * 4 + jj > ty * 4 + i) s[i][jj] = -1e30f;
        }

        // Online softmax update (row groups of 16 lanes: xor-shuffle 8,4,2,1)
#pragma unroll
        for (int i = 0; i < 4; i++) {
            float rm = fmaxf(fmaxf(s[i][0], s[i][1]), fmaxf(s[i][2], s[i][3]));
#pragma unroll
            for (int o = 8; o >= 1; o >>= 1)
                rm = fmaxf(rm, __shfl_xor_sync(0xffffffffu, rm, o));
            float mn = fmaxf(mrow[i], rm);
            float alpha = __expf(mrow[i] - mn);
            float rs = 0.f;
#pragma unroll
            for (int jj = 0; jj < 4; jj++) {
                float p = __expf(s[i][jj] - mn);
                Ps[(ty * 4 + i) * SMLD + tx * 4 + jj] = p;
                rs += p;
            }
#pragma unroll
            for (int o = 8; o >= 1; o >>= 1)
                rs += __shfl_xor_sync(0xffffffffu, rs, o);
            lrow[i] = lrow[i] * alpha + rs;
            mrow[i] = mn;
#pragma unroll
            for (int c = 0; c < 4; c++) acc[i][c] *= alpha;
        }
        __syncthreads();

        // acc += P * V
#pragma unroll 8
        for (int jj = 0; jj < 64; jj++) {
            float pv[4], vv[4];
#pragma unroll
            for (int i = 0; i < 4; i++)  pv[i] = Ps[(ty * 4 + i) * SMLD + jj];
#pragma unroll
            for (int c = 0; c < 4; c++)  vv[c] = Vs[jj * SMLD + tx * 4 + c];
#pragma unroll
            for (int i = 0; i < 4; i++)
#pragma unroll
                for (int c = 0; c < 4; c++)
                    acc[i][c] += pv[i] * vv[c];
        }
        __syncthreads();   // protect Ks/Vs/Ps before next iteration's loads
    }

    // Normalize and write O[b, q, h*dk + c]
    float* Og = O + base + (size_t)qb * 64 * D_MODEL;
#pragma unroll
    for (int i = 0; i < 4; i++) {
        int r = ty * 4 + i;
        float inv = 1.f / lrow[i];
        float4 o4 = make_float4(acc[i][0] * inv, acc[i][1] * inv,
                                acc[i][2] * inv, acc[i][3] * inv);
        *(float4*)(Og + (size_t)r * D_MODEL + tx * 4) = o4;
    }
}

// ----------------------------------------------------------------------------
// kernel_launch
// Inputs: x [2,2048,1024], q_heads [16,64,1024], k_heads, v_heads, output_proj [1024,1024]
// Output: [2,2048,1024] fp32
// ----------------------------------------------------------------------------
extern "C" void kernel_launch(void* const* d_in, const int* in_sizes, int n_in,
                              void* d_out, int out_size)
{
    const float* x  = (const float*)d_in[0];
    const float* wq = (const float*)d_in[1];
    const float* wk = (const float*)d_in[2];
    const float* wv = (const float*)d_in[3];
    const float* wo = (const float*)d_in[4];
    float* out = (float*)d_out;

    float *q, *k, *v, *o;
    cudaGetSymbolAddress((void**)&q, g_Q);
    cudaGetSymbolAddress((void**)&k, g_K);
    cudaGetSymbolAddress((void**)&v, g_V);
    cudaGetSymbolAddress((void**)&o, g_O);

    // QKV projections: [4096,1024] x [1024,1024]^T each.
    // q_heads flattened row-major is exactly [h*dk, d] — GEMM B operand as-is.
    dim3 gg(D_MODEL / 128, MROWS / 128);   // (8, 32)
    sgemm_nt<<<gg, 256>>>(x, wq, q, MROWS, D_MODEL, D_MODEL);
    sgemm_nt<<<gg, 256>>>(x, wk, k, MROWS, D_MODEL, D_MODEL);
    sgemm_nt<<<gg, 256>>>(x, wv, v, MROWS, D_MODEL, D_MODEL);

    // Causal flash attention
    const int smem_bytes = 4 * 64 * SMLD * sizeof(float);   // 66,560 B
    cudaFuncSetAttribute(attn_fwd, cudaFuncAttributeMaxDynamicSharedMemorySize,
                         smem_bytes);
    dim3 ga(SEQ / 64, NHEADS, BATCH);      // (32, 16, 2)
    attn_fwd<<<ga, 256, smem_bytes>>>(q, k, v, o);

    // Output projection: out[b,s,d] = sum_k O[b,s,k] * P[d,k]  ->  A*B^T again
    sgemm_nt<<<gg, 256>>>(o, wo, out, MROWS, D_MODEL, D_MODEL);
}

// round 2
// speedup vs baseline: 1.0375x; 1.0375x over previous
#include <cuda_runtime.h>
#include <math.h>

#define D_MODEL 1024
#define NHEADS  16
#define DK      64
#define BATCH   2
#define SEQ     2048
#define MROWS   (BATCH*SEQ)   // 4096

// Scratch (device globals: allocation-free per harness rules)
__device__ float g_Q[MROWS * D_MODEL];
__device__ float g_K[MROWS * D_MODEL];
__device__ float g_V[MROWS * D_MODEL];
__device__ float g_O[MROWS * D_MODEL];

// ----------------------------------------------------------------------------
// SGEMM: C[M,N] = A[M,K] * B[N,K]^T, double-buffered smem pipeline.
// 128x128 block, BK=16, 256 threads, 8x8 micro-tile, 1 sync per K-step.
// ----------------------------------------------------------------------------
__global__ __launch_bounds__(256, 2)
void sgemm_nt(const float* __restrict__ A, const float* __restrict__ Bm,
              float* __restrict__ C, int M, int N, int K)
{
    __shared__ float As[2][16][128];
    __shared__ float Bs[2][16][128];

    const int tid = threadIdx.x;
    const int ty  = tid >> 4;        // 0..15
    const int tx  = tid & 15;        // 0..15

    const float* Ab = A  + (size_t)blockIdx.y * 128 * K;
    const float* Bb = Bm + (size_t)blockIdx.x * 128 * K;

    // loader coords: each thread handles 2 float4 per operand per tile
    const int lr0 = tid >> 2;              // 0..63
    const int lc  = (tid & 3) * 4;         // 0,4,8,12

    float acc[8][8];
#pragma unroll
    for (int i = 0; i < 8; i++)
#pragma unroll
        for (int j = 0; j < 8; j++) acc[i][j] = 0.f;

    // Prologue: load tile 0 directly to smem buffer 0
#pragma unroll
    for (int l = 0; l < 2; l++) {
        int r = lr0 + l * 64;
        float4 va = *(const float4*)(Ab + (size_t)r * K + lc);
        As[0][lc + 0][r] = va.x; As[0][lc + 1][r] = va.y;
        As[0][lc + 2][r] = va.z; As[0][lc + 3][r] = va.w;
        float4 vb = *(const float4*)(Bb + (size_t)r * K + lc);
        Bs[0][lc + 0][r] = vb.x; Bs[0][lc + 1][r] = vb.y;
        Bs[0][lc + 2][r] = vb.z; Bs[0][lc + 3][r] = vb.w;
    }
    __syncthreads();

    for (int kk = 0; kk < K; kk += 16) {
        const int buf = (kk >> 4) & 1;
        const bool pf = (kk + 16) < K;

        // Prefetch next tile into registers (latency overlapped with compute)
        float4 nva[2], nvb[2];
        if (pf) {
#pragma unroll
            for (int l = 0; l < 2; l++) {
                int r = lr0 + l * 64;
                nva[l] = *(const float4*)(Ab + (size_t)r * K + kk + 16 + lc);
                nvb[l] = *(const float4*)(Bb + (size_t)r * K + kk + 16 + lc);
            }
        }

        // Compute current tile
#pragma unroll
        for (int k = 0; k < 16; k++) {
            float a[8], b[8];
            *(float4*)(a)     = *(const float4*)(&As[buf][k][ty * 8]);
            *(float4*)(a + 4) = *(const float4*)(&As[buf][k][ty * 8 + 4]);
            *(float4*)(b)     = *(const float4*)(&Bs[buf][k][tx * 8]);
            *(float4*)(b + 4) = *(const float4*)(&Bs[buf][k][tx * 8 + 4]);
#pragma unroll
            for (int i = 0; i < 8; i++)
#pragma unroll
                for (int j = 0; j < 8; j++)
                    acc[i][j] += a[i] * b[j];
        }

        // Store prefetched tile into the other buffer
        if (pf) {
            const int nb = buf ^ 1;
#pragma unroll
            for (int l = 0; l < 2; l++) {
                int r = lr0 + l * 64;
                As[nb][lc + 0][r] = nva[l].x; As[nb][lc + 1][r] = nva[l].y;
                As[nb][lc + 2][r] = nva[l].z; As[nb][lc + 3][r] = nva[l].w;
                Bs[nb][lc + 0][r] = nvb[l].x; Bs[nb][lc + 1][r] = nvb[l].y;
                Bs[nb][lc + 2][r] = nvb[l].z; Bs[nb][lc + 3][r] = nvb[l].w;
            }
        }
        __syncthreads();
    }

#pragma unroll
    for (int i = 0; i < 8; i++) {
        float* cp = C + (size_t)(blockIdx.y * 128 + ty * 8 + i) * N
                      + blockIdx.x * 128 + tx * 8;
        *(float4*)(cp)     = make_float4(acc[i][0], acc[i][1], acc[i][2], acc[i][3]);
        *(float4*)(cp + 4) = make_float4(acc[i][4], acc[i][5], acc[i][6], acc[i][7]);
    }
}

// ----------------------------------------------------------------------------
// Flash attention (fp32, causal). Br=Bc=128, dk=64, 256 threads.
// S: 8x8 micro-tile; PV: 8x4 micro-tile. P stored transposed in smem so the
// PV loop reads it with conflict-free LDS.128.
// Q/K/V laid out [b, s, h*dk]; per-head row stride = D_MODEL.
// ----------------------------------------------------------------------------
__global__ __launch_bounds__(256, 1)
void attn_fwd(const float* __restrict__ Q, const float* __restrict__ K,
              const float* __restrict__ V, float* __restrict__ O)
{
    extern __shared__ float smem[];
    float* Qs = smem;                    // [64][128]  k-major: Qs[k*128+row]
    float* Ks = Qs + 64 * 128;           // [64][128]  k-major: Ks[k*128+col]
    float* Vs = Ks + 64 * 128;           // [128][64]  row-major
    float* Ps = Vs + 128 * 64;           // [128][128] P^T: Ps[col*128+row]

    const int qb = (gridDim.x - 1) - blockIdx.x;  // heavy blocks launch first
    const int h  = blockIdx.y;
    const int b  = blockIdx.z;
    const int tid = threadIdx.x;
    const int ty = tid >> 4;             // 0..15 -> rows ty*8..+7
    const int tx = tid & 15;             // 0..15 -> S cols tx*8..+7, PV cols tx*4..+3

    const size_t base = (size_t)b * SEQ * D_MODEL + (size_t)h * DK;
    const float* Qg = Q + base + (size_t)qb * 128 * D_MODEL;
    const float scale = 0.125f;          // 1/sqrt(64)

    // Load Q tile (128 rows x 64 cols), pre-scaled, stored k-major.
#pragma unroll
    for (int l = 0; l < 8; l++) {
        int idx = tid + l * 256;         // 0..2047 float4 slots
        int r = idx >> 4;                // 0..127
        int c = (idx & 15) * 4;          // 0..60
        float4 v = *(const float4*)(Qg + (size_t)r * D_MODEL + c);
        Qs[(c + 0) * 128 + r] = v.x * scale;
        Qs[(c + 1) * 128 + r] = v.y * scale;
        Qs[(c + 2) * 128 + r] = v.z * scale;
        Qs[(c + 3) * 128 + r] = v.w * scale;
    }

    float mrow[8], lrow[8], acc[8][4];
#pragma unroll
    for (int i = 0; i < 8; i++) {
        mrow[i] = -1e30f; lrow[i] = 0.f;
#pragma unroll
        for (int c = 0; c < 4; c++) acc[i][c] = 0.f;
    }
    __syncthreads();

    for (int j = 0; j <= qb; j++) {
        const float* Kg = K + base + (size_t)j * 128 * D_MODEL;
        const float* Vg = V + base + (size_t)j * 128 * D_MODEL;
        // Load K (k-major) and V (row-major) tiles
#pragma unroll
        for (int l = 0; l < 8; l++) {
            int idx = tid + l * 256;
            int r = idx >> 4;
            int c = (idx & 15) * 4;
            float4 vk = *(const float4*)(Kg + (size_t)r * D_MODEL + c);
            Ks[(c + 0) * 128 + r] = vk.x;
            Ks[(c + 1) * 128 + r] = vk.y;
            Ks[(c + 2) * 128 + r] = vk.z;
            Ks[(c + 3) * 128 + r] = vk.w;
            float4 vv = *(const float4*)(Vg + (size_t)r * D_MODEL + c);
            *(float4*)(&Vs[r * 64 + c]) = vv;
        }
        __syncthreads();

        // ---- S = Q * K^T : 8x8 micro-tile, GEMM-style ----
        float s[8][8];
#pragma unroll
        for (int i = 0; i < 8; i++)
#pragma unroll
            for (int jj = 0; jj < 8; jj++) s[i][jj] = 0.f;

#pragma unroll 4
        for (int k = 0; k < 64; k++) {
            float a[8], bk[8];
            *(float4*)(a)      = *(const float4*)(&Qs[k * 128 + ty * 8]);
            *(float4*)(a + 4)  = *(const float4*)(&Qs[k * 128 + ty * 8 + 4]);
            *(float4*)(bk)     = *(const float4*)(&Ks[k * 128 + tx * 8]);
            *(float4*)(bk + 4) = *(const float4*)(&Ks[k * 128 + tx * 8 + 4]);
#pragma unroll
            for (int i = 0; i < 8; i++)
#pragma unroll
                for (int jj = 0; jj < 8; jj++)
                    s[i][jj] += a[i] * bk[jj];
        }

        // Causal mask on the diagonal tile only
        if (j == qb) {
#pragma unroll
            for (int i = 0; i < 8; i++)
#pragma unroll
                for (int jj = 0; jj < 8; jj++)
                    if (tx * 8 + jj > ty * 8 + i) s[i][jj] = -1e30f;
        }

        // ---- Online softmax (row groups = 16 lanes sharing ty) ----
#pragma unroll
        for (int i = 0; i < 8; i++) {
            float rm = s[i][0];
#pragma unroll
            for (int jj = 1; jj < 8; jj++) rm = fmaxf(rm, s[i][jj]);
#pragma unroll
            for (int o = 8; o >= 1; o >>= 1)
                rm = fmaxf(rm, __shfl_xor_sync(0xffffffffu, rm, o));
            float mn = fmaxf(mrow[i], rm);
            float alpha = __expf(mrow[i] - mn);
            float rs = 0.f;
#pragma unroll
            for (int jj = 0; jj < 8; jj++) {
                float p = __expf(s[i][jj] - mn);
                s[i][jj] = p;
                rs += p;
            }
#pragma unroll
            for (int o = 8; o >= 1; o >>= 1)
                rs += __shfl_xor_sync(0xffffffffu, rs, o);
            lrow[i] = lrow[i] * alpha + rs;
            mrow[i] = mn;
#pragma unroll
            for (int c = 0; c < 4; c++) acc[i][c] *= alpha;
        }

        // Write P^T to smem (reads in PV are conflict-free; writes are rare)
#pragma unroll
        for (int jj = 0; jj < 8; jj++) {
            int col = tx * 8 + jj;
            *(float4*)(&Ps[col * 128 + ty * 8]) =
                make_float4(s[0][jj], s[1][jj], s[2][jj], s[3][jj]);
            *(float4*)(&Ps[col * 128 + ty * 8 + 4]) =
                make_float4(s[4][jj], s[5][jj], s[6][jj], s[7][jj]);
        }
        __syncthreads();

        // ---- acc += P * V : 8x4 micro-tile ----
#pragma unroll 4
        for (int jj = 0; jj < 128; jj++) {
            float pv[8], vv[4];
            *(float4*)(pv)     = *(const float4*)(&Ps[jj * 128 + ty * 8]);
            *(float4*)(pv + 4) = *(const float4*)(&Ps[jj * 128 + ty * 8 + 4]);
            *(float4*)(vv)     = *(const float4*)(&Vs[jj * 64 + tx * 4]);
#pragma unroll
            for (int i = 0; i < 8; i++)
#pragma unroll
                for (int c = 0; c < 4; c++)
                    acc[i][c] += pv[i] * vv[c];
        }
        __syncthreads();   // protect Ks/Vs/Ps before next iteration's loads
    }

    // Normalize and write O[b, q, h*dk + c]
    float* Og = O + base + (size_t)qb * 128 * D_MODEL;
#pragma unroll
    for (int i = 0; i < 8; i++) {
        int r = ty * 8 + i;
        float inv = 1.f / lrow[i];
        *(float4*)(Og + (size_t)r * D_MODEL + tx * 4) =
            make_float4(acc[i][0] * inv, acc[i][1] * inv,
                        acc[i][2] * inv, acc[i][3] * inv);
    }
}

// ----------------------------------------------------------------------------
// kernel_launch
// Inputs: x [2,2048,1024], q_heads [16,64,1024], k_heads, v_heads, output_proj [1024,1024]
// Output: [2,2048,1024] fp32
// ----------------------------------------------------------------------------
extern "C" void kernel_launch(void* const* d_in, const int* in_sizes, int n_in,
                              void* d_out, int out_size)
{
    const float* x  = (const float*)d_in[0];
    const float* wq = (const float*)d_in[1];
    const float* wk = (const float*)d_in[2];
    const float* wv = (const float*)d_in[3];
    const float* wo = (const float*)d_in[4];
    float* out = (float*)d_out;

    float *q, *k, *v, *o;
    cudaGetSymbolAddress((void**)&q, g_Q);
    cudaGetSymbolAddress((void**)&k, g_K);
    cudaGetSymbolAddress((void**)&v, g_V);
    cudaGetSymbolAddress((void**)&o, g_O);

    // QKV projections: [4096,1024] x [1024,1024]^T each.
    dim3 gg(D_MODEL / 128, MROWS / 128);   // (8, 32)
    sgemm_nt<<<gg, 256>>>(x, wq, q, MROWS, D_MODEL, D_MODEL);
    sgemm_nt<<<gg, 256>>>(x, wk, k, MROWS, D_MODEL, D_MODEL);
    sgemm_nt<<<gg, 256>>>(x, wv, v, MROWS, D_MODEL, D_MODEL);

    // Causal flash attention, 128x128 tiles
    const int smem_bytes = (64 * 128 + 64 * 128 + 128 * 64 + 128 * 128) * sizeof(float); // 160 KB
    cudaFuncSetAttribute(attn_fwd, cudaFuncAttributeMaxDynamicSharedMemorySize,
                         smem_bytes);
    dim3 ga(SEQ / 128, NHEADS, BATCH);     // (16, 16, 2)
    attn_fwd<<<ga, 256, smem_bytes>>>(q, k, v, o);

    // Output projection: out = O * P^T
    sgemm_nt<<<gg, 256>>>(o, wo, out, MROWS, D_MODEL, D_MODEL);
}

// round 3
// speedup vs baseline: 2.5039x; 2.4135x over previous
#include <cuda_runtime.h>
#include <math.h>

#define D_MODEL 1024
#define NHEADS  16
#define DK      64
#define BATCH   2
#define SEQ     2048
#define MROWS   (BATCH*SEQ)   // 4096

// Scratch (device globals: allocation-free per harness rules)
__device__ float g_Q[MROWS * D_MODEL];
__device__ float g_K[MROWS * D_MODEL];
__device__ float g_V[MROWS * D_MODEL];
__device__ float g_O[MROWS * D_MODEL];

// ---------------------------------------------------------------------------
// tf32 helpers
// ---------------------------------------------------------------------------
__device__ __forceinline__ unsigned f2tf32(float x) {
    unsigned u;
    asm("cvt.rna.tf32.f32 %0, %1;" : "=r"(u) : "f"(x));
    return u;
}
__device__ __forceinline__ float ex2f(float x) {
    float r;
    asm("ex2.approx.f32 %0, %1;" : "=f"(r) : "f"(x));
    return r;
}
// D = A*B + D, m16n8k8, A row-major, B col-major, fp32 accum
__device__ __forceinline__ void mma_tf32(float* c, const unsigned* a, const unsigned* b) {
    asm volatile(
        "mma.sync.aligned.m16n8k8.row.col.f32.tf32.tf32.f32 "
        "{%0,%1,%2,%3}, {%4,%5,%6,%7}, {%8,%9}, {%0,%1,%2,%3};\n"
        : "+f"(c[0]), "+f"(c[1]), "+f"(c[2]), "+f"(c[3])
        : "r"(a[0]), "r"(a[1]), "r"(a[2]), "r"(a[3]),
          "r"(b[0]), "r"(b[1]));
}

// ---------------------------------------------------------------------------
// tf32 GEMM: C[M,N] = A[M,K] * B[N,K]^T
// 128x128 block, BK=16, 256 threads (8 warps, 2Mx4N), warp tile 64x32.
// Smem k-major, stride 136 -> all fragment loads conflict-free ((8t+g)%32).
// ---------------------------------------------------------------------------
#define GSTR 136

__global__ __launch_bounds__(256)
void gemm_tf32(const float* __restrict__ A, const float* __restrict__ Bm,
               float* __restrict__ C, int M, int N, int K)
{
    __shared__ unsigned As[2][16 * GSTR];
    __shared__ unsigned Bs[2][16 * GSTR];

    const int tid  = threadIdx.x;
    const int warp = tid >> 5;
    const int lane = tid & 31;
    const int g    = lane >> 2;       // 0..7
    const int t    = lane & 3;        // 0..3
    const int wy   = warp & 1;        // M dir (2)
    const int wx   = warp >> 1;       // N dir (4)

    const float* Ab = A  + (size_t)blockIdx.y * 128 * K;
    const float* Bb = Bm + (size_t)blockIdx.x * 128 * K;

    const int lr = tid >> 2;          // 0..63
    const int lc = (tid & 3) * 4;     // 0,4,8,12

    float c[4][4][4];
#pragma unroll
    for (int mi = 0; mi < 4; mi++)
#pragma unroll
        for (int ni = 0; ni < 4; ni++)
#pragma unroll
            for (int r = 0; r < 4; r++) c[mi][ni][r] = 0.f;

    // Prologue: tile 0 -> buffer 0
#pragma unroll
    for (int l = 0; l < 2; l++) {
        int r = lr + l * 64;
        float4 va = *(const float4*)(Ab + (size_t)r * K + lc);
        As[0][(lc + 0) * GSTR + r] = f2tf32(va.x);
        As[0][(lc + 1) * GSTR + r] = f2tf32(va.y);
        As[0][(lc + 2) * GSTR + r] = f2tf32(va.z);
        As[0][(lc + 3) * GSTR + r] = f2tf32(va.w);
        float4 vb = *(const float4*)(Bb + (size_t)r * K + lc);
        Bs[0][(lc + 0) * GSTR + r] = f2tf32(vb.x);
        Bs[0][(lc + 1) * GSTR + r] = f2tf32(vb.y);
        Bs[0][(lc + 2) * GSTR + r] = f2tf32(vb.z);
        Bs[0][(lc + 3) * GSTR + r] = f2tf32(vb.w);
    }
    __syncthreads();

    for (int kk = 0; kk < K; kk += 16) {
        const int buf = (kk >> 4) & 1;
        const bool pf = (kk + 16) < K;

        float4 nva[2], nvb[2];
        if (pf) {
#pragma unroll
            for (int l = 0; l < 2; l++) {
                int r = lr + l * 64;
                nva[l] = *(const float4*)(Ab + (size_t)r * K + kk + 16 + lc);
                nvb[l] = *(const float4*)(Bb + (size_t)r * K + kk + 16 + lc);
            }
        }

#pragma unroll
        for (int ks = 0; ks < 16; ks += 8) {
            const int k0 = ks + t;
            unsigned a[4][4], b[4][2];
#pragma unroll
            for (int mi = 0; mi < 4; mi++) {
                int r = wy * 64 + mi * 16 + g;
                a[mi][0] = As[buf][k0 * GSTR + r];
                a[mi][1] = As[buf][k0 * GSTR + r + 8];
                a[mi][2] = As[buf][(k0 + 4) * GSTR + r];
                a[mi][3] = As[buf][(k0 + 4) * GSTR + r + 8];
            }
#pragma unroll
            for (int ni = 0; ni < 4; ni++) {
                int n = wx * 32 + ni * 8 + g;
                b[ni][0] = Bs[buf][k0 * GSTR + n];
                b[ni][1] = Bs[buf][(k0 + 4) * GSTR + n];
            }
#pragma unroll
            for (int mi = 0; mi < 4; mi++)
#pragma unroll
                for (int ni = 0; ni < 4; ni++)
                    mma_tf32(c[mi][ni], a[mi], b[ni]);
        }

        if (pf) {
            const int nb = buf ^ 1;
#pragma unroll
            for (int l = 0; l < 2; l++) {
                int r = lr + l * 64;
                As[nb][(lc + 0) * GSTR + r] = f2tf32(nva[l].x);
                As[nb][(lc + 1) * GSTR + r] = f2tf32(nva[l].y);
                As[nb][(lc + 2) * GSTR + r] = f2tf32(nva[l].z);
                As[nb][(lc + 3) * GSTR + r] = f2tf32(nva[l].w);
                Bs[nb][(lc + 0) * GSTR + r] = f2tf32(nvb[l].x);
                Bs[nb][(lc + 1) * GSTR + r] = f2tf32(nvb[l].y);
                Bs[nb][(lc + 2) * GSTR + r] = f2tf32(nvb[l].z);
                Bs[nb][(lc + 3) * GSTR + r] = f2tf32(nvb[l].w);
            }
        }
        __syncthreads();
    }

    // Epilogue
#pragma unroll
    for (int mi = 0; mi < 4; mi++) {
        int row = blockIdx.y * 128 + wy * 64 + mi * 16 + g;
#pragma unroll
        for (int ni = 0; ni < 4; ni++) {
            int col = blockIdx.x * 128 + wx * 32 + ni * 8 + 2 * t;
            *(float2*)(C + (size_t)row * N + col) =
                make_float2(c[mi][ni][0], c[mi][ni][1]);
            *(float2*)(C + (size_t)(row + 8) * N + col) =
                make_float2(c[mi][ni][2], c[mi][ni][3]);
        }
    }
}

// ---------------------------------------------------------------------------
// Flash attention, tf32 tensor cores. Br=Bc=128, dk=64, 256 threads.
// Each warp owns 16 q-rows end-to-end. Softmax in exp2 domain.
// ---------------------------------------------------------------------------
#define QSTR 136
#define VSTR 72

__global__ __launch_bounds__(256)
void attn_fwd(const float* __restrict__ Q, const float* __restrict__ K,
              const float* __restrict__ V, float* __restrict__ O)
{
    extern __shared__ unsigned sm[];
    unsigned* Qs = sm;                   // [64][136] k-major
    unsigned* Ks = Qs + 64 * QSTR;       // [64][136] k-major
    unsigned* Vs = Ks + 64 * QSTR;       // [128][72] row-major
    unsigned* Ps = Vs + 128 * VSTR;      // [128][136] row-major (warp-private bands)

    const int qb = (gridDim.x - 1) - blockIdx.x;  // heavy blocks first
    const int h  = blockIdx.y;
    const int b  = blockIdx.z;
    const int tid  = threadIdx.x;
    const int warp = tid >> 5;
    const int lane = tid & 31;
    const int g    = lane >> 2;
    const int t    = lane & 3;

    const size_t base = (size_t)b * SEQ * D_MODEL + (size_t)h * DK;
    const float* Qg = Q + base + (size_t)qb * 128 * D_MODEL;
    // fold 1/sqrt(dk) and log2(e) into Q so softmax runs in exp2 domain
    const float qscale = 0.125f * 1.4426950408889634f;

    // Load Q tile (128 x 64) k-major, prescaled, tf32
#pragma unroll
    for (int l = 0; l < 8; l++) {
        int idx = tid + l * 256;
        int r = idx >> 4;                // 0..127
        int cc = (idx & 15) * 4;         // 0..60
        float4 v = *(const float4*)(Qg + (size_t)r * D_MODEL + cc);
        Qs[(cc + 0) * QSTR + r] = f2tf32(v.x * qscale);
        Qs[(cc + 1) * QSTR + r] = f2tf32(v.y * qscale);
        Qs[(cc + 2) * QSTR + r] = f2tf32(v.z * qscale);
        Qs[(cc + 3) * QSTR + r] = f2tf32(v.w * qscale);
    }
    __syncthreads();

    // Preload Q fragments for this warp's 16 rows (held all kernel)
    unsigned qa[8][4];
    const int rq = warp * 16 + g;
#pragma unroll
    for (int kt = 0; kt < 8; kt++) {
        int k0 = kt * 8 + t;
        qa[kt][0] = Qs[k0 * QSTR + rq];
        qa[kt][1] = Qs[k0 * QSTR + rq + 8];
        qa[kt][2] = Qs[(k0 + 4) * QSTR + rq];
        qa[kt][3] = Qs[(k0 + 4) * QSTR + rq + 8];
    }

    float m0 = -1e30f, m1 = -1e30f, l0 = 0.f, l1 = 0.f;
    float o[8][4];
#pragma unroll
    for (int ni = 0; ni < 8; ni++)
#pragma unroll
        for (int r = 0; r < 4; r++) o[ni][r] = 0.f;

    const int prow0 = warp * 16 + g;
    const int prow1 = prow0 + 8;

    for (int j = 0; j <= qb; j++) {
        const float* Kg = K + base + (size_t)j * 128 * D_MODEL;
        const float* Vg = V + base + (size_t)j * 128 * D_MODEL;
#pragma unroll
        for (int l = 0; l < 8; l++) {
            int idx = tid + l * 256;
            int r = idx >> 4;
            int cc = (idx & 15) * 4;
            float4 vk = *(const float4*)(Kg + (size_t)r * D_MODEL + cc);
            Ks[(cc + 0) * QSTR + r] = f2tf32(vk.x);
            Ks[(cc + 1) * QSTR + r] = f2tf32(vk.y);
            Ks[(cc + 2) * QSTR + r] = f2tf32(vk.z);
            Ks[(cc + 3) * QSTR + r] = f2tf32(vk.w);
            float4 vv = *(const float4*)(Vg + (size_t)r * D_MODEL + cc);
            Vs[r * VSTR + cc + 0] = f2tf32(vv.x);
            Vs[r * VSTR + cc + 1] = f2tf32(vv.y);
            Vs[r * VSTR + cc + 2] = f2tf32(vv.z);
            Vs[r * VSTR + cc + 3] = f2tf32(vv.w);
        }
        __syncthreads();

        // ---- S = Q * K^T : 16 n-tiles x 8 k-tiles of m16n8k8 ----
        float s[16][4];
#pragma unroll
        for (int ni = 0; ni < 16; ni++) {
            s[ni][0] = 0.f; s[ni][1] = 0.f; s[ni][2] = 0.f; s[ni][3] = 0.f;
            int n = ni * 8 + g;
#pragma unroll
            for (int kt = 0; kt < 8; kt++) {
                int k0 = kt * 8 + t;
                unsigned bb[2];
                bb[0] = Ks[k0 * QSTR + n];
                bb[1] = Ks[(k0 + 4) * QSTR + n];
                mma_tf32(s[ni], qa[kt], bb);
            }
        }

        // Causal mask (diagonal block only); relative row/col comparison
        if (j == qb) {
#pragma unroll
            for (int ni = 0; ni < 16; ni++) {
                int cb = ni * 8 + 2 * t;
                if (cb     > prow0) s[ni][0] = -1e30f;
                if (cb + 1 > prow0) s[ni][1] = -1e30f;
                if (cb     > prow1) s[ni][2] = -1e30f;
                if (cb + 1 > prow1) s[ni][3] = -1e30f;
            }
        }

        // ---- Online softmax (exp2 domain). Rows g / g+8; quad = 4 lanes ----
        float rm0 = -1e30f, rm1 = -1e30f;
#pragma unroll
        for (int ni = 0; ni < 16; ni++) {
            rm0 = fmaxf(rm0, fmaxf(s[ni][0], s[ni][1]));
            rm1 = fmaxf(rm1, fmaxf(s[ni][2], s[ni][3]));
        }
        rm0 = fmaxf(rm0, __shfl_xor_sync(0xffffffffu, rm0, 1));
        rm0 = fmaxf(rm0, __shfl_xor_sync(0xffffffffu, rm0, 2));
        rm1 = fmaxf(rm1, __shfl_xor_sync(0xffffffffu, rm1, 1));
        rm1 = fmaxf(rm1, __shfl_xor_sync(0xffffffffu, rm1, 2));

        float mn0 = fmaxf(m0, rm0), mn1 = fmaxf(m1, rm1);
        float a0 = ex2f(m0 - mn0), a1 = ex2f(m1 - mn1);
        float rs0 = 0.f, rs1 = 0.f;
#pragma unroll
        for (int ni = 0; ni < 16; ni++) {
            int col = ni * 8 + 2 * t;
            float p00 = ex2f(s[ni][0] - mn0);
            float p01 = ex2f(s[ni][1] - mn0);
            float p10 = ex2f(s[ni][2] - mn1);
            float p11 = ex2f(s[ni][3] - mn1);
            rs0 += p00 + p01;
            rs1 += p10 + p11;
            Ps[prow0 * QSTR + col]     = f2tf32(p00);
            Ps[prow0 * QSTR + col + 1] = f2tf32(p01);
            Ps[prow1 * QSTR + col]     = f2tf32(p10);
            Ps[prow1 * QSTR + col + 1] = f2tf32(p11);
        }
        rs0 += __shfl_xor_sync(0xffffffffu, rs0, 1);
        rs0 += __shfl_xor_sync(0xffffffffu, rs0, 2);
        rs1 += __shfl_xor_sync(0xffffffffu, rs1, 1);
        rs1 += __shfl_xor_sync(0xffffffffu, rs1, 2);
        l0 = l0 * a0 + rs0;  m0 = mn0;
        l1 = l1 * a1 + rs1;  m1 = mn1;
#pragma unroll
        for (int ni = 0; ni < 8; ni++) {
            o[ni][0] *= a0; o[ni][1] *= a0;
            o[ni][2] *= a1; o[ni][3] *= a1;
        }
        __syncwarp();   // P band is warp-private: warp-level ordering suffices

        // ---- O += P * V : 16 k-tiles x 8 n-tiles ----
#pragma unroll
        for (int kt = 0; kt < 16; kt++) {
            int k0 = kt * 8 + t;
            unsigned pa[4];
            pa[0] = Ps[prow0 * QSTR + k0];
            pa[1] = Ps[prow1 * QSTR + k0];
            pa[2] = Ps[prow0 * QSTR + k0 + 4];
            pa[3] = Ps[prow1 * QSTR + k0 + 4];
#pragma unroll
            for (int ni = 0; ni < 8; ni++) {
                unsigned vb[2];
                int n = ni * 8 + g;
                vb[0] = Vs[k0 * VSTR + n];
                vb[1] = Vs[(k0 + 4) * VSTR + n];
                mma_tf32(o[ni], pa, vb);
            }
        }
        __syncthreads();  // protect Ks/Vs before next iteration's loads
    }

    // Normalize and write O
    float inv0 = 1.f / l0, inv1 = 1.f / l1;
    float* Og = O + base + (size_t)qb * 128 * D_MODEL;
#pragma unroll
    for (int ni = 0; ni < 8; ni++) {
        int col = ni * 8 + 2 * t;
        *(float2*)(Og + (size_t)prow0 * D_MODEL + col) =
            make_float2(o[ni][0] * inv0, o[ni][1] * inv0);
        *(float2*)(Og + (size_t)prow1 * D_MODEL + col) =
            make_float2(o[ni][2] * inv1, o[ni][3] * inv1);
    }
}

// ---------------------------------------------------------------------------
// kernel_launch
// ---------------------------------------------------------------------------
extern "C" void kernel_launch(void* const* d_in, const int* in_sizes, int n_in,
                              void* d_out, int out_size)
{
    const float* x  = (const float*)d_in[0];
    const float* wq = (const float*)d_in[1];
    const float* wk = (const float*)d_in[2];
    const float* wv = (const float*)d_in[3];
    const float* wo = (const float*)d_in[4];
    float* out = (float*)d_out;

    float *q, *k, *v, *o;
    cudaGetSymbolAddress((void**)&q, g_Q);
    cudaGetSymbolAddress((void**)&k, g_K);
    cudaGetSymbolAddress((void**)&v, g_V);
    cudaGetSymbolAddress((void**)&o, g_O);

    dim3 gg(D_MODEL / 128, MROWS / 128);   // (8, 32)
    gemm_tf32<<<gg, 256>>>(x, wq, q, MROWS, D_MODEL, D_MODEL);
    gemm_tf32<<<gg, 256>>>(x, wk, k, MROWS, D_MODEL, D_MODEL);
    gemm_tf32<<<gg, 256>>>(x, wv, v, MROWS, D_MODEL, D_MODEL);

    const int smem_bytes = (64 * QSTR * 2 + 128 * VSTR + 128 * QSTR) * 4; // 176,128 B
    cudaFuncSetAttribute(attn_fwd, cudaFuncAttributeMaxDynamicSharedMemorySize,
                         smem_bytes);
    dim3 ga(SEQ / 128, NHEADS, BATCH);     // (16, 16, 2)
    attn_fwd<<<ga, 256, smem_bytes>>>(q, k, v, o);

    gemm_tf32<<<gg, 256>>>(o, wo, out, MROWS, D_MODEL, D_MODEL);
}